// round 6
// baseline (speedup 1.0000x reference)
#include <cuda_runtime.h>
#include <math.h>

#define NB 128
#define NT 512

typedef unsigned long long u64;

constexpr int S_LEN = 1024;
constexpr int B_SZ  = 64;
constexpr int F_DIM = 128;
constexpr int H_DIM = 512;
constexpr int V_DIM = 64;
constexpr int T_LEN = 64;
constexpr int HPB   = 4;                 // hidden units per block (16 gate rows)

constexpr int PSR = 68;                  // psum row stride: 272B = 16B-aligned + bank stagger
constexpr int PSW = 16 * PSR;            // floats per k-segment
constexpr int W_FLOATS  = 512 * 16;      // Wsm [k][16 rows]
constexpr int P_FLOATS  = 16 * PSW;      // psum [16 seg][16 row][PSR]
constexpr int XP_FLOATS = 2 * 1024;      // xproj double buffer
constexpr int LSC_FLOATS = 640;
constexpr int SMEM_FLOATS = W_FLOATS + P_FLOATS + XP_FLOATS + 16 + LSC_FLOATS;
constexpr int SMEM_BYTES  = SMEM_FLOATS * 4;

// ---------------- persistent device state ----------------
__device__ float g_sigT[S_LEN * F_DIM * B_SZ];        // [t][f][b]
__device__ float g_xproj[(size_t)NB * S_LEN * 1024];  // [blk][t][row*64+b]
__device__ float g_hT[2][H_DIM * B_SZ];               // [k][b] double buffered
__device__ float g_outWT[H_DIM * V_DIM];              // [k][v]
__device__ int   g_tok[B_SZ];
__device__ u64 g_barCount, g_barGen;                  // full barrier (monotonic)
__device__ u64 g_ckCount[4], g_ckGen[4];              // per-chunk barriers (monotonic)

// ---------------- sync primitives ----------------
__device__ __forceinline__ u64 ld_acq(const u64* p) {
    u64 v; asm volatile("ld.acquire.gpu.u64 %0, [%1];" : "=l"(v) : "l"(p) : "memory");
    return v;
}
__device__ __forceinline__ void st_rel(u64* p, u64 v) {
    asm volatile("st.release.gpu.u64 [%0], %1;" :: "l"(p), "l"(v) : "memory");
}
__device__ __forceinline__ void bar_arrive(u64 gen) {
    __syncthreads();
    if (threadIdx.x == 0) {
        __threadfence();
        u64 v = atomicAdd(&g_barCount, 1ULL);
        if (v == gen * (u64)NB - 1ULL) { __threadfence(); st_rel(&g_barGen, gen); }
    }
}
__device__ __forceinline__ void bar_wait(u64 gen) {
    if (threadIdx.x == 0) { while (ld_acq(&g_barGen) < gen) { } }
    __syncthreads();
}

__device__ __forceinline__ float sigmoidf(float x) { return 1.0f / (1.0f + expf(-x)); }

// ---------------- packed f32x2 ----------------
__device__ __forceinline__ u64 pack2(float x) {
    unsigned int u = __float_as_uint(x);
    u64 r; asm("mov.b64 %0, {%1, %1};" : "=l"(r) : "r"(u));
    return r;
}
__device__ __forceinline__ void fma2(u64& d, u64 a, u64 b) {
    asm("fma.rn.f32x2 %0, %1, %2, %0;" : "+l"(d) : "l"(a), "l"(b));
}

// ---------------- cp.async (xproj prefetch) ----------------
__device__ __forceinline__ void cp16(unsigned int dst, const float* src) {
    asm volatile("cp.async.ca.shared.global [%0], [%1], 16;" :: "r"(dst), "l"(src));
}
#define CP_COMMIT() asm volatile("cp.async.commit_group;" ::: "memory")
#define CP_WAIT(n)  asm volatile("cp.async.wait_group %0;" :: "n"(n) : "memory")

// ---------------- 32-k accumulate: 4 rows x 8 batches per thread ----------------
__device__ __forceinline__ void cw32(const float* __restrict__ Wc,
                                     const float* __restrict__ zg,
                                     u64 acc[16]) {
#pragma unroll 8
    for (int kk = 0; kk < 32; ++kk) {
        ulonglong2 za = *(const ulonglong2*)(zg + kk * 64);      // b0..b0+3
        ulonglong2 zb = *(const ulonglong2*)(zg + kk * 64 + 4);  // b0+4..b0+7
        float4 w = *(const float4*)(Wc + kk * 16);               // 4 rows
        u64 w0 = pack2(w.x), w1 = pack2(w.y), w2 = pack2(w.z), w3 = pack2(w.w);
        fma2(acc[0],  w0, za.x); fma2(acc[1],  w0, za.y);
        fma2(acc[2],  w0, zb.x); fma2(acc[3],  w0, zb.y);
        fma2(acc[4],  w1, za.x); fma2(acc[5],  w1, za.y);
        fma2(acc[6],  w1, zb.x); fma2(acc[7],  w1, zb.y);
        fma2(acc[8],  w2, za.x); fma2(acc[9],  w2, za.y);
        fma2(acc[10], w2, zb.x); fma2(acc[11], w2, zb.y);
        fma2(acc[12], w3, za.x); fma2(acc[13], w3, za.y);
        fma2(acc[14], w3, zb.x); fma2(acc[15], w3, zb.y);
    }
}

__global__ void __launch_bounds__(NT, 1) lstm_seq2seq_kernel(
    const float* __restrict__ sig, const int* __restrict__ tgt,
    const float* __restrict__ eWih, const float* __restrict__ eWhh,
    const float* __restrict__ eBih, const float* __restrict__ eBhh,
    const float* __restrict__ dWih, const float* __restrict__ dWhh,
    const float* __restrict__ dBih, const float* __restrict__ dBhh,
    const float* __restrict__ oW, const float* __restrict__ oB,
    float* __restrict__ out)
{
    extern __shared__ float sm[];
    float* Wsm     = sm;                       // [k][16]
    float* psum    = Wsm + W_FLOATS;           // [seg][row][PSR]
    float* xp      = psum + P_FLOATS;          // [2][1024]
    float* bias_sm = xp + XP_FLOATS;           // [16]
    float* lsc     = bias_sm + 16;             // logits scratch

    const int tid  = threadIdx.x;
    const int blk  = blockIdx.x;
    const int lane = tid & 31;
    const int ws   = tid >> 5;                 // warp 0..15 (k-segment)
    const int rt   = lane & 3;                 // row group
    const int bt   = lane >> 2;                // batch group
    const int b0   = bt * 8;
    const int hb   = blk * HPB;
    const int b    = tid & 63;                 // update: batch
    const int hh_u = (tid >> 6) & 3;           // update: hidden (tid<256)
    const int gtid = blk * NT + tid;
    const int cmine = blk >> 5;                // chunk this block produces
    const int cw    = ws >> 2;                 // chunk this warp consumes

    // barrier bases (stable: prior launch fully complete, no writes until after init bar)
    u64 gen     = *(volatile u64*)&g_barGen;
    u64 c0_own  = *(volatile u64*)&g_ckCount[cmine];
    u64 gk_own  = *(volatile u64*)&g_ckGen[cw];
    u64 gk_t    = (tid < 4) ? *(volatile u64*)&g_ckGen[tid] : 0ULL;

    // ---------------- init: signal transpose [b][t][f] -> [t][f][b] ----------------
    {
        float* tileS = psum;                   // 64x64 tile, pad 65 (scalar accesses)
        for (int tile = blk; tile < S_LEN * 2; tile += NB) {
            int t = tile >> 1, f0 = (tile & 1) * 64;
            __syncthreads();
            for (int i = tid; i < 4096; i += NT) {
                int bb = i >> 6, ff = i & 63;
                tileS[ff * 65 + bb] = sig[((size_t)bb * S_LEN + t) * F_DIM + f0 + ff];
            }
            __syncthreads();
            for (int i = tid; i < 4096; i += NT) {
                int ff = i >> 6, bb = i & 63;
                g_sigT[(size_t)t * 8192 + (f0 + ff) * 64 + bb] = tileS[ff * 65 + bb];
            }
        }
    }
    for (int i = gtid; i < H_DIM * B_SZ; i += NB * NT) {
        g_hT[0][i] = 0.0f; g_hT[1][i] = 0.0f;
    }
    for (int i = gtid; i < H_DIM * V_DIM; i += NB * NT) {
        int v = i & 63, k2 = i >> 6;
        g_outWT[i] = oW[v * H_DIM + k2];
    }
    if (gtid < B_SZ) g_tok[gtid] = tgt[gtid * T_LEN];

    bar_arrive(++gen);
    bar_wait(gen);

    // ---------------- precompute xproj = W_ih @ x_t for all t (sync-free) --------
    __syncthreads();
    for (int i = tid; i < F_DIM * 16; i += NT) {            // Wsm = W_ih [128][16]
        int k2 = i >> 4, r = i & 15;
        int j = (r >> 2) * H_DIM + hb + (r & 3);
        Wsm[i] = eWih[j * F_DIM + k2];
    }
    __syncthreads();
    {
        u64 acc[16];
        for (int ti = 0; ti < S_LEN / 16; ++ti) {
            int t = ws + ti * 16;
#pragma unroll
            for (int i = 0; i < 16; ++i) acc[i] = 0ULL;
#pragma unroll 1
            for (int c = 0; c < 4; ++c)
                cw32(Wsm + c * 32 * 16 + rt * 4,
                     g_sigT + (size_t)t * 8192 + c * 2048 + b0, acc);
            float* xd = g_xproj + ((size_t)blk * S_LEN + t) * 1024;
#pragma unroll
            for (int i = 0; i < 4; ++i) {
                int r = rt * 4 + i;
                *(ulonglong2*)(xd + r * 64 + b0)     = make_ulonglong2(acc[i*4+0], acc[i*4+1]);
                *(ulonglong2*)(xd + r * 64 + b0 + 4) = make_ulonglong2(acc[i*4+2], acc[i*4+3]);
            }
        }
    }
    bar_arrive(++gen);
    bar_wait(gen);

    // ---------------- stage encoder W_hh + bias ----------------
    for (int i = tid; i < H_DIM * 16; i += NT) {
        int k2 = i >> 4, r = i & 15;
        int j = (r >> 2) * H_DIM + hb + (r & 3);
        Wsm[i] = eWhh[j * H_DIM + k2];
    }
    if (tid < 16) {
        int j = (tid >> 2) * H_DIM + hb + (tid & 3);
        bias_sm[tid] = eBih[j] + eBhh[j];
    }
    __syncthreads();

    float c_reg = 0.0f;
    int cur = 0;
    u64 sgen = 0;
    u64 acc[16];

    // prefetch xproj(t=0)
    if (tid < 256) cp16((unsigned int)__cvta_generic_to_shared(xp) + tid * 16,
                        g_xproj + (size_t)blk * S_LEN * 1024 + tid * 4);
    CP_COMMIT();

    // ---------------- encoder loop ----------------
    for (int t = 0; t < S_LEN; ++t) {
        // prefetch xproj(t+1)
        if (tid < 256 && t + 1 < S_LEN)
            cp16((unsigned int)__cvta_generic_to_shared(xp + ((t + 1) & 1) * 1024) + tid * 16,
                 g_xproj + ((size_t)blk * S_LEN + (t + 1)) * 1024 + tid * 4);
        CP_COMMIT();

        // wait for this warp's h chunk
        if (lane == 0) { while (ld_acq(&g_ckGen[cw]) < gk_own + sgen) { } }
        __syncwarp();

#pragma unroll
        for (int i = 0; i < 16; ++i) acc[i] = 0ULL;
        cw32(Wsm + ws * 32 * 16 + rt * 4, g_hT[cur] + ws * 2048 + b0, acc);

        // psum (16B-aligned: PSR*4 = 272B multiple of 16)
#pragma unroll
        for (int i = 0; i < 4; ++i) {
            int r = rt * 4 + i;
            *(ulonglong2*)(psum + ws * PSW + r * PSR + b0)     = make_ulonglong2(acc[i*4+0], acc[i*4+1]);
            *(ulonglong2*)(psum + ws * PSW + r * PSR + b0 + 4) = make_ulonglong2(acc[i*4+2], acc[i*4+3]);
        }
        CP_WAIT(1);
        __syncthreads();

        if (tid < 256) {
            const float* xpb = xp + (t & 1) * 1024;
            float gv[4];
#pragma unroll
            for (int g = 0; g < 4; ++g) {
                int r = g * 4 + hh_u;
                float s = bias_sm[r] + xpb[r * 64 + b];
#pragma unroll
                for (int s2 = 0; s2 < 16; ++s2) s += psum[s2 * PSW + r * PSR + b];
                gv[g] = s;
            }
            float cn = sigmoidf(gv[1]) * c_reg + sigmoidf(gv[0]) * tanhf(gv[2]);
            float hn = sigmoidf(gv[3]) * tanhf(cn);
            c_reg = cn;
            g_hT[cur ^ 1][(hb + hh_u) * 64 + b] = hn;
        }
        __syncthreads();
        ++sgen;
        if (tid == 0) {
            __threadfence();
            u64 v = atomicAdd(&g_ckCount[cmine], 1ULL);
            if (v == c0_own + 32ULL * sgen - 1ULL) {
                __threadfence();
                st_rel(&g_ckGen[cmine], gk_own + sgen);
            }
        }
        cur ^= 1;
    }

    // ---------------- stage decoder W_hh + bias ----------------
    __syncthreads();
    for (int i = tid; i < H_DIM * 16; i += NT) {
        int k2 = i >> 4, r = i & 15;
        int j = (r >> 2) * H_DIM + hb + (r & 3);
        Wsm[i] = dWhh[j * H_DIM + k2];
    }
    if (tid < 16) {
        int j = (tid >> 2) * H_DIM + hb + (tid & 3);
        bias_sm[tid] = dBih[j] + dBhh[j];
    }
    __syncthreads();

    // ---------------- decoder loop ----------------
    for (int s = 0; s < T_LEN; ++s) {
        // one-hot input gather (relu identity), early-issued
        float xg[4];
        if (tid < 256) {
            int tokb = g_tok[b];
#pragma unroll
            for (int g = 0; g < 4; ++g)
                xg[g] = __ldg(&dWih[((size_t)(g * H_DIM + hb + hh_u)) * V_DIM + tokb]);
        }

        if (lane == 0) { while (ld_acq(&g_ckGen[cw]) < gk_own + sgen) { } }
        __syncwarp();

#pragma unroll
        for (int i = 0; i < 16; ++i) acc[i] = 0ULL;
        cw32(Wsm + ws * 32 * 16 + rt * 4, g_hT[cur] + ws * 2048 + b0, acc);

#pragma unroll
        for (int i = 0; i < 4; ++i) {
            int r = rt * 4 + i;
            *(ulonglong2*)(psum + ws * PSW + r * PSR + b0)     = make_ulonglong2(acc[i*4+0], acc[i*4+1]);
            *(ulonglong2*)(psum + ws * PSW + r * PSR + b0 + 4) = make_ulonglong2(acc[i*4+2], acc[i*4+3]);
        }
        __syncthreads();

        if (tid < 256) {
            float gv[4];
#pragma unroll
            for (int g = 0; g < 4; ++g) {
                int r = g * 4 + hh_u;
                float sv = bias_sm[r] + xg[g];
#pragma unroll
                for (int s2 = 0; s2 < 16; ++s2) sv += psum[s2 * PSW + r * PSR + b];
                gv[g] = sv;
            }
            float cn = sigmoidf(gv[1]) * c_reg + sigmoidf(gv[0]) * tanhf(gv[2]);
            float hn = sigmoidf(gv[3]) * tanhf(cn);
            c_reg = cn;
            g_hT[cur ^ 1][(hb + hh_u) * 64 + b] = hn;
        }
        __syncthreads();
        ++sgen;
        if (tid == 0) {
            __threadfence();
            u64 v = atomicAdd(&g_ckCount[cmine], 1ULL);
            if (v == c0_own + 32ULL * sgen - 1ULL) {
                __threadfence();
                st_rel(&g_ckGen[cmine], gk_own + sgen);
            }
        }
        cur ^= 1;

        // logits + argmax (blocks 0..63, one batch row each)
        if (blk < B_SZ) {
            if (tid < 4) { while (ld_acq(&g_ckGen[tid]) < gk_t + sgen) { } }
            __syncthreads();
            int bb = blk;
            int v = tid & 63, part = tid >> 6;           // 8 parts x 64 k
            const float* hp = &g_hT[cur][part * 64 * 64 + bb];
            const float* wp = &g_outWT[part * 64 * 64 + v];
            float pr = 0.0f;
#pragma unroll 8
            for (int kk = 0; kk < 64; ++kk)
                pr += __ldg(&hp[kk * 64]) * __ldg(&wp[kk * 64]);
            lsc[part * 64 + v] = pr;
            __syncthreads();
            if (part == 0) {
                float logit = oB[v];
#pragma unroll
                for (int p2 = 0; p2 < 8; ++p2) logit += lsc[p2 * 64 + v];
                lsc[512 + v] = logit;
                out[((size_t)bb * T_LEN + s) * V_DIM + v] = logit;
            }
            __syncthreads();
            if (tid == 0) {
                float best = lsc[512];
                int bi = 0;
#pragma unroll 1
                for (int v2 = 1; v2 < 64; ++v2) {
                    float x = lsc[512 + v2];
                    if (x > best) { best = x; bi = v2; }
                }
                g_tok[bb] = bi;
            }
        }
        bar_arrive(++gen);
        bar_wait(gen);                                   // tok + logits visible
    }

    // ---------------- log_softmax ----------------
    {
        int wid = gtid >> 5;
        int ln  = tid & 31;
        for (int r = wid; r < B_SZ * T_LEN; r += (NB * NT) / 32) {
            float* row = out + (size_t)r * V_DIM;
            float x0 = row[ln], x1 = row[ln + 32];
            float m = fmaxf(x0, x1);
#pragma unroll
            for (int o = 16; o > 0; o >>= 1)
                m = fmaxf(m, __shfl_xor_sync(0xffffffffu, m, o));
            float e = expf(x0 - m) + expf(x1 - m);
#pragma unroll
            for (int o = 16; o > 0; o >>= 1)
                e += __shfl_xor_sync(0xffffffffu, e, o);
            float lse = m + logf(e);
            row[ln] = x0 - lse;
            row[ln + 32] = x1 - lse;
        }
    }
}

extern "C" void kernel_launch(void* const* d_in, const int* in_sizes, int n_in,
                              void* d_out, int out_size) {
    (void)in_sizes; (void)n_in; (void)out_size;
    cudaFuncSetAttribute(lstm_seq2seq_kernel,
                         cudaFuncAttributeMaxDynamicSharedMemorySize, SMEM_BYTES);
    lstm_seq2seq_kernel<<<NB, NT, SMEM_BYTES>>>(
        (const float*)d_in[0],  (const int*)d_in[1],
        (const float*)d_in[2],  (const float*)d_in[3],
        (const float*)d_in[4],  (const float*)d_in[5],
        (const float*)d_in[6],  (const float*)d_in[7],
        (const float*)d_in[8],  (const float*)d_in[9],
        (const float*)d_in[10], (const float*)d_in[11],
        (float*)d_out);
}

// round 7
// speedup vs baseline: 1.1187x; 1.1187x over previous
#include <cuda_runtime.h>
#include <math.h>

#define NB 128
#define NT 512

typedef unsigned long long u64;

constexpr int S_LEN = 1024;
constexpr int B_SZ  = 64;
constexpr int F_DIM = 128;
constexpr int H_DIM = 512;
constexpr int V_DIM = 64;
constexpr int T_LEN = 64;
constexpr int HPB   = 4;                 // hidden units per block (16 gate rows)

constexpr int PSR = 68;                  // psum row stride: 272B = 16B-aligned + bank stagger
constexpr int PSW = 16 * PSR;            // floats per k-segment
constexpr int W_FLOATS  = 512 * 16;      // Wsm [k][16 rows]
constexpr int P_FLOATS  = 16 * PSW;      // psum [16 seg][16 row][PSR]
constexpr int XP_FLOATS = 2 * 1024;      // xproj double buffer
constexpr int LSC_FLOATS = 640;
constexpr int SMEM_FLOATS = W_FLOATS + P_FLOATS + XP_FLOATS + 16 + LSC_FLOATS;
constexpr int SMEM_BYTES  = SMEM_FLOATS * 4;

// ---------------- persistent device state ----------------
__device__ float g_sigT[S_LEN * F_DIM * B_SZ];        // [t][f][b]
__device__ float g_xproj[(size_t)NB * S_LEN * 1024];  // [blk][t][row*64+b]
__device__ float g_hT[2][H_DIM * B_SZ];               // [k][b] double buffered
__device__ float g_outWT[H_DIM * V_DIM];              // [k][v]
__device__ int   g_tok[B_SZ];
__device__ u64 g_barCount, g_barGen;                  // full barrier (monotonic)

// ---------------- sync primitives (single poller per block) ----------------
__device__ __forceinline__ u64 ld_acq(const u64* p) {
    u64 v; asm volatile("ld.acquire.gpu.u64 %0, [%1];" : "=l"(v) : "l"(p) : "memory");
    return v;
}
__device__ __forceinline__ void st_rel(u64* p, u64 v) {
    asm volatile("st.release.gpu.u64 [%0], %1;" :: "l"(p), "l"(v) : "memory");
}
__device__ __forceinline__ void bar_arrive(u64 gen) {
    __syncthreads();
    if (threadIdx.x == 0) {
        __threadfence();
        u64 v = atomicAdd(&g_barCount, 1ULL);
        if (v == gen * (u64)NB - 1ULL) { __threadfence(); st_rel(&g_barGen, gen); }
    }
}
__device__ __forceinline__ void bar_wait(u64 gen) {
    if (threadIdx.x == 0) { while (ld_acq(&g_barGen) < gen) { } }
    __syncthreads();
}

__device__ __forceinline__ float sigmoidf(float x) { return 1.0f / (1.0f + expf(-x)); }

// ---------------- packed f32x2 ----------------
__device__ __forceinline__ u64 pack2(float x) {
    unsigned int u = __float_as_uint(x);
    u64 r; asm("mov.b64 %0, {%1, %1};" : "=l"(r) : "r"(u));
    return r;
}
__device__ __forceinline__ void fma2(u64& d, u64 a, u64 b) {
    asm("fma.rn.f32x2 %0, %1, %2, %0;" : "+l"(d) : "l"(a), "l"(b));
}

// ---------------- cp.async (xproj prefetch) ----------------
__device__ __forceinline__ void cp16(unsigned int dst, const float* src) {
    asm volatile("cp.async.ca.shared.global [%0], [%1], 16;" :: "r"(dst), "l"(src));
}
#define CP_COMMIT() asm volatile("cp.async.commit_group;" ::: "memory")
#define CP_WAIT(n)  asm volatile("cp.async.wait_group %0;" :: "n"(n) : "memory")

// ---------------- 32-k accumulate: 4 rows x 8 batches (2 per u64) ----------------
__device__ __forceinline__ void cw32(const float* __restrict__ Wc,
                                     const float* __restrict__ zg,
                                     u64 acc[16]) {
#pragma unroll 8
    for (int kk = 0; kk < 32; ++kk) {
        ulonglong2 za = *(const ulonglong2*)(zg + kk * 64);      // b0..b0+3
        ulonglong2 zb = *(const ulonglong2*)(zg + kk * 64 + 4);  // b0+4..b0+7
        float4 w = *(const float4*)(Wc + kk * 16);               // 4 rows
        u64 w0 = pack2(w.x), w1 = pack2(w.y), w2 = pack2(w.z), w3 = pack2(w.w);
        fma2(acc[0],  w0, za.x); fma2(acc[1],  w0, za.y);
        fma2(acc[2],  w0, zb.x); fma2(acc[3],  w0, zb.y);
        fma2(acc[4],  w1, za.x); fma2(acc[5],  w1, za.y);
        fma2(acc[6],  w1, zb.x); fma2(acc[7],  w1, zb.y);
        fma2(acc[8],  w2, za.x); fma2(acc[9],  w2, za.y);
        fma2(acc[10], w2, zb.x); fma2(acc[11], w2, zb.y);
        fma2(acc[12], w3, za.x); fma2(acc[13], w3, za.y);
        fma2(acc[14], w3, zb.x); fma2(acc[15], w3, zb.y);
    }
}

__global__ void __launch_bounds__(NT, 1) lstm_seq2seq_kernel(
    const float* __restrict__ sig, const int* __restrict__ tgt,
    const float* __restrict__ eWih, const float* __restrict__ eWhh,
    const float* __restrict__ eBih, const float* __restrict__ eBhh,
    const float* __restrict__ dWih, const float* __restrict__ dWhh,
    const float* __restrict__ dBih, const float* __restrict__ dBhh,
    const float* __restrict__ oW, const float* __restrict__ oB,
    float* __restrict__ out)
{
    extern __shared__ float sm[];
    float* Wsm     = sm;                       // [k][16]
    float* psum    = Wsm + W_FLOATS;           // [seg][row][PSR]
    float* xp      = psum + P_FLOATS;          // [2][1024]
    float* bias_sm = xp + XP_FLOATS;           // [16]
    float* lsc     = bias_sm + 16;             // logits scratch

    const int tid  = threadIdx.x;
    const int blk  = blockIdx.x;
    const int lane = tid & 31;
    const int ws   = tid >> 5;                 // warp 0..15 (k-segment)
    const int rt   = lane & 3;                 // row group
    const int bt   = lane >> 2;                // batch group
    const int b0   = bt * 8;
    const int hb   = blk * HPB;
    const int b    = tid & 63;                 // update: batch
    const int hh_u = (tid >> 6) & 3;           // update: hidden (tid<256)
    const int gtid = blk * NT + tid;

    // barrier base (stable: prior launch fully complete)
    u64 gen = *(volatile u64*)&g_barGen;

    // ---------------- init: signal transpose [b][t][f] -> [t][f][b] ----------------
    {
        float* tileS = psum;                   // 64x64 tile, pad 65 (scalar accesses)
        for (int tile = blk; tile < S_LEN * 2; tile += NB) {
            int t = tile >> 1, f0 = (tile & 1) * 64;
            __syncthreads();
            for (int i = tid; i < 4096; i += NT) {
                int bb = i >> 6, ff = i & 63;
                tileS[ff * 65 + bb] = sig[((size_t)bb * S_LEN + t) * F_DIM + f0 + ff];
            }
            __syncthreads();
            for (int i = tid; i < 4096; i += NT) {
                int ff = i >> 6, bb = i & 63;
                g_sigT[(size_t)t * 8192 + (f0 + ff) * 64 + bb] = tileS[ff * 65 + bb];
            }
        }
    }
    for (int i = gtid; i < H_DIM * B_SZ; i += NB * NT) {
        g_hT[0][i] = 0.0f; g_hT[1][i] = 0.0f;
    }
    for (int i = gtid; i < H_DIM * V_DIM; i += NB * NT) {
        int v = i & 63, k2 = i >> 6;
        g_outWT[i] = oW[v * H_DIM + k2];
    }
    if (gtid < B_SZ) g_tok[gtid] = tgt[gtid * T_LEN];

    bar_arrive(++gen);
    bar_wait(gen);

    // ---------------- precompute xproj = W_ih @ x_t for all t (sync-free) --------
    __syncthreads();
    for (int i = tid; i < F_DIM * 16; i += NT) {            // Wsm = W_ih [128][16]
        int k2 = i >> 4, r = i & 15;
        int j = (r >> 2) * H_DIM + hb + (r & 3);
        Wsm[i] = eWih[j * F_DIM + k2];
    }
    __syncthreads();
    {
        u64 acc[16];
        for (int ti = 0; ti < S_LEN / 16; ++ti) {
            int t = ws + ti * 16;
#pragma unroll
            for (int i = 0; i < 16; ++i) acc[i] = 0ULL;
#pragma unroll 1
            for (int c = 0; c < 4; ++c)
                cw32(Wsm + c * 32 * 16 + rt * 4,
                     g_sigT + (size_t)t * 8192 + c * 2048 + b0, acc);
            float* xd = g_xproj + ((size_t)blk * S_LEN + t) * 1024;
#pragma unroll
            for (int i = 0; i < 4; ++i) {
                int r = rt * 4 + i;
                *(ulonglong2*)(xd + r * 64 + b0)     = make_ulonglong2(acc[i*4+0], acc[i*4+1]);
                *(ulonglong2*)(xd + r * 64 + b0 + 4) = make_ulonglong2(acc[i*4+2], acc[i*4+3]);
            }
        }
    }
    bar_arrive(++gen);
    bar_wait(gen);

    // ---------------- stage encoder W_hh + bias ----------------
    for (int i = tid; i < H_DIM * 16; i += NT) {
        int k2 = i >> 4, r = i & 15;
        int j = (r >> 2) * H_DIM + hb + (r & 3);
        Wsm[i] = eWhh[j * H_DIM + k2];
    }
    if (tid < 16) {
        int j = (tid >> 2) * H_DIM + hb + (tid & 3);
        bias_sm[tid] = eBih[j] + eBhh[j];
    }
    __syncthreads();

    float c_reg = 0.0f;
    int cur = 0;
    u64 acc[16];

    // prefetch xproj(t=0)
    if (tid < 256) cp16((unsigned int)__cvta_generic_to_shared(xp) + tid * 16,
                        g_xproj + (size_t)blk * S_LEN * 1024 + tid * 4);
    CP_COMMIT();

    // ---------------- encoder loop: ONE full barrier per step ----------------
    for (int t = 0; t < S_LEN; ++t) {
        // prefetch xproj(t+1)
        if (tid < 256 && t + 1 < S_LEN)
            cp16((unsigned int)__cvta_generic_to_shared(xp + ((t + 1) & 1) * 1024) + tid * 16,
                 g_xproj + ((size_t)blk * S_LEN + (t + 1)) * 1024 + tid * 4);
        CP_COMMIT();

        bar_wait(gen);                         // h(t) visible (no-op at t=0)

#pragma unroll
        for (int i = 0; i < 16; ++i) acc[i] = 0ULL;
        cw32(Wsm + ws * 32 * 16 + rt * 4, g_hT[cur] + ws * 2048 + b0, acc);

        // psum (16B-aligned: PSR*4 = 272B multiple of 16)
#pragma unroll
        for (int i = 0; i < 4; ++i) {
            int r = rt * 4 + i;
            *(ulonglong2*)(psum + ws * PSW + r * PSR + b0)     = make_ulonglong2(acc[i*4+0], acc[i*4+1]);
            *(ulonglong2*)(psum + ws * PSW + r * PSR + b0 + 4) = make_ulonglong2(acc[i*4+2], acc[i*4+3]);
        }
        CP_WAIT(1);
        __syncthreads();

        if (tid < 256) {
            const float* xpb = xp + (t & 1) * 1024;
            float gv[4];
#pragma unroll
            for (int g = 0; g < 4; ++g) {
                int r = g * 4 + hh_u;
                float s = bias_sm[r] + xpb[r * 64 + b];
#pragma unroll
                for (int s2 = 0; s2 < 16; ++s2) s += psum[s2 * PSW + r * PSR + b];
                gv[g] = s;
            }
            float cn = sigmoidf(gv[1]) * c_reg + sigmoidf(gv[0]) * tanhf(gv[2]);
            float hn = sigmoidf(gv[3]) * tanhf(cn);
            c_reg = cn;
            g_hT[cur ^ 1][(hb + hh_u) * 64 + b] = hn;
        }
        bar_arrive(++gen);                     // includes __syncthreads
        cur ^= 1;
    }

    // ---------------- stage decoder W_hh + bias ----------------
    bar_wait(gen);                             // final h visible
    __syncthreads();
    for (int i = tid; i < H_DIM * 16; i += NT) {
        int k2 = i >> 4, r = i & 15;
        int j = (r >> 2) * H_DIM + hb + (r & 3);
        Wsm[i] = dWhh[j * H_DIM + k2];
    }
    if (tid < 16) {
        int j = (tid >> 2) * H_DIM + hb + (tid & 3);
        bias_sm[tid] = dBih[j] + dBhh[j];
    }
    __syncthreads();

    // ---------------- decoder loop ----------------
    for (int s = 0; s < T_LEN; ++s) {
        // one-hot input gather (relu identity); tok visible from last barrier
        float xg[4];
        if (tid < 256) {
            int tokb = g_tok[b];
#pragma unroll
            for (int g = 0; g < 4; ++g)
                xg[g] = __ldg(&dWih[((size_t)(g * H_DIM + hb + hh_u)) * V_DIM + tokb]);
        }

#pragma unroll
        for (int i = 0; i < 16; ++i) acc[i] = 0ULL;
        cw32(Wsm + ws * 32 * 16 + rt * 4, g_hT[cur] + ws * 2048 + b0, acc);

#pragma unroll
        for (int i = 0; i < 4; ++i) {
            int r = rt * 4 + i;
            *(ulonglong2*)(psum + ws * PSW + r * PSR + b0)     = make_ulonglong2(acc[i*4+0], acc[i*4+1]);
            *(ulonglong2*)(psum + ws * PSW + r * PSR + b0 + 4) = make_ulonglong2(acc[i*4+2], acc[i*4+3]);
        }
        __syncthreads();

        if (tid < 256) {
            float gv[4];
#pragma unroll
            for (int g = 0; g < 4; ++g) {
                int r = g * 4 + hh_u;
                float sv = bias_sm[r] + xg[g];
#pragma unroll
                for (int s2 = 0; s2 < 16; ++s2) sv += psum[s2 * PSW + r * PSR + b];
                gv[g] = sv;
            }
            float cn = sigmoidf(gv[1]) * c_reg + sigmoidf(gv[0]) * tanhf(gv[2]);
            float hn = sigmoidf(gv[3]) * tanhf(cn);
            c_reg = cn;
            g_hT[cur ^ 1][(hb + hh_u) * 64 + b] = hn;
        }
        bar_arrive(++gen);
        bar_wait(gen);                         // new h visible everywhere
        cur ^= 1;

        // logits + argmax (blocks 0..63, one batch row each)
        if (blk < B_SZ) {
            int bb = blk;
            int v = tid & 63, part = tid >> 6;           // 8 parts x 64 k
            const float* hp = &g_hT[cur][part * 64 * 64 + bb];
            const float* wp = &g_outWT[part * 64 * 64 + v];
            float pr = 0.0f;
#pragma unroll 8
            for (int kk = 0; kk < 64; ++kk)
                pr += __ldg(&hp[kk * 64]) * __ldg(&wp[kk * 64]);
            lsc[part * 64 + v] = pr;
            __syncthreads();
            if (part == 0) {
                float logit = oB[v];
#pragma unroll
                for (int p2 = 0; p2 < 8; ++p2) logit += lsc[p2 * 64 + v];
                lsc[512 + v] = logit;
                out[((size_t)bb * T_LEN + s) * V_DIM + v] = logit;
            }
            __syncthreads();
            if (tid == 0) {
                float best = lsc[512];
                int bi = 0;
#pragma unroll 1
                for (int v2 = 1; v2 < 64; ++v2) {
                    float x = lsc[512 + v2];
                    if (x > best) { best = x; bi = v2; }
                }
                g_tok[bb] = bi;
            }
        }
        bar_arrive(++gen);
        bar_wait(gen);                         // tok + logits visible
    }

    // ---------------- log_softmax ----------------
    {
        int wid = gtid >> 5;
        int ln  = tid & 31;
        for (int r = wid; r < B_SZ * T_LEN; r += (NB * NT) / 32) {
            float* row = out + (size_t)r * V_DIM;
            float x0 = row[ln], x1 = row[ln + 32];
            float m = fmaxf(x0, x1);
#pragma unroll
            for (int o = 16; o > 0; o >>= 1)
                m = fmaxf(m, __shfl_xor_sync(0xffffffffu, m, o));
            float e = expf(x0 - m) + expf(x1 - m);
#pragma unroll
            for (int o = 16; o > 0; o >>= 1)
                e += __shfl_xor_sync(0xffffffffu, e, o);
            float lse = m + logf(e);
            row[ln] = x0 - lse;
            row[ln + 32] = x1 - lse;
        }
    }
}

extern "C" void kernel_launch(void* const* d_in, const int* in_sizes, int n_in,
                              void* d_out, int out_size) {
    (void)in_sizes; (void)n_in; (void)out_size;
    cudaFuncSetAttribute(lstm_seq2seq_kernel,
                         cudaFuncAttributeMaxDynamicSharedMemorySize, SMEM_BYTES);
    lstm_seq2seq_kernel<<<NB, NT, SMEM_BYTES>>>(
        (const float*)d_in[0],  (const int*)d_in[1],
        (const float*)d_in[2],  (const float*)d_in[3],
        (const float*)d_in[4],  (const float*)d_in[5],
        (const float*)d_in[6],  (const float*)d_in[7],
        (const float*)d_in[8],  (const float*)d_in[9],
        (const float*)d_in[10], (const float*)d_in[11],
        (float*)d_out);
}